// round 1
// baseline (speedup 1.0000x reference)
#include <cuda_runtime.h>
#include <cstdint>

// Problem constants
#define M_DIM 16384
#define N_DIM 4096
#define K_DIM 1024
#define TOPK  409

// -------------------------------------------------------------------------
// Global flag: does x contain any negative value? (decides bipolar transform)
// -------------------------------------------------------------------------
__device__ int g_has_neg;

__global__ void init_flags_kernel() { g_has_neg = 0; }

__global__ void scan_neg_kernel(const float4* __restrict__ x, int n4) {
    int idx = blockIdx.x * blockDim.x + threadIdx.x;
    int stride = gridDim.x * blockDim.x;
    int found = 0;
    for (int i = idx; i < n4; i += stride) {
        float4 v = x[i];
        if (v.x < 0.f || v.y < 0.f || v.z < 0.f || v.w < 0.f) { found = 1; break; }
    }
    if (found) g_has_neg = 1;
}

// -------------------------------------------------------------------------
// SGEMM: C[M,N] = A[M,K] * B[N,K]^T   (both row-major, K contiguous)
// BM=128, BN=128, BK=16, 256 threads, 8x8 microtile per thread.
// Applies bipolar transform (x-0.5)*2 to A on load iff g_has_neg == 0.
// -------------------------------------------------------------------------
#define BM 128
#define BN 128
#define BK 16

__global__ void __launch_bounds__(256)
gemm_kernel(const float* __restrict__ A, const float* __restrict__ B,
            float* __restrict__ C) {
    __shared__ float As[BK][BM];
    __shared__ float Bs[BK][BN];

    const int bm = blockIdx.y * BM;
    const int bn = blockIdx.x * BN;
    const int tid = threadIdx.x;
    const int tx = tid % 16;   // n direction
    const int ty = tid / 16;   // m direction

    const bool bip = (g_has_neg == 0);

    // Loader mapping: 256 threads, each loads 2x float4 from A and B per tile.
    const int lrow = tid >> 2;          // 0..63
    const int lcol = (tid & 3) * 4;     // 0,4,8,12

    const float* Ag = A + (size_t)(bm + lrow) * K_DIM + lcol;
    const float* Bg = B + (size_t)(bn + lrow) * K_DIM + lcol;

    float acc[8][8];
#pragma unroll
    for (int i = 0; i < 8; i++)
#pragma unroll
        for (int j = 0; j < 8; j++) acc[i][j] = 0.f;

    for (int k0 = 0; k0 < K_DIM; k0 += BK) {
        float4 a0 = *(const float4*)(Ag + k0);
        float4 a1 = *(const float4*)(Ag + (size_t)64 * K_DIM + k0);
        float4 b0 = *(const float4*)(Bg + k0);
        float4 b1 = *(const float4*)(Bg + (size_t)64 * K_DIM + k0);

        if (bip) {
            a0.x = (a0.x - 0.5f) * 2.0f; a0.y = (a0.y - 0.5f) * 2.0f;
            a0.z = (a0.z - 0.5f) * 2.0f; a0.w = (a0.w - 0.5f) * 2.0f;
            a1.x = (a1.x - 0.5f) * 2.0f; a1.y = (a1.y - 0.5f) * 2.0f;
            a1.z = (a1.z - 0.5f) * 2.0f; a1.w = (a1.w - 0.5f) * 2.0f;
        }

        As[lcol + 0][lrow] = a0.x; As[lcol + 1][lrow] = a0.y;
        As[lcol + 2][lrow] = a0.z; As[lcol + 3][lrow] = a0.w;
        As[lcol + 0][lrow + 64] = a1.x; As[lcol + 1][lrow + 64] = a1.y;
        As[lcol + 2][lrow + 64] = a1.z; As[lcol + 3][lrow + 64] = a1.w;

        Bs[lcol + 0][lrow] = b0.x; Bs[lcol + 1][lrow] = b0.y;
        Bs[lcol + 2][lrow] = b0.z; Bs[lcol + 3][lrow] = b0.w;
        Bs[lcol + 0][lrow + 64] = b1.x; Bs[lcol + 1][lrow + 64] = b1.y;
        Bs[lcol + 2][lrow + 64] = b1.z; Bs[lcol + 3][lrow + 64] = b1.w;

        __syncthreads();

#pragma unroll
        for (int k = 0; k < BK; k++) {
            float ra[8], rb[8];
            *(float4*)&ra[0] = *(const float4*)&As[k][ty * 8 + 0];
            *(float4*)&ra[4] = *(const float4*)&As[k][ty * 8 + 4];
            *(float4*)&rb[0] = *(const float4*)&Bs[k][tx * 8 + 0];
            *(float4*)&rb[4] = *(const float4*)&Bs[k][tx * 8 + 4];
#pragma unroll
            for (int i = 0; i < 8; i++)
#pragma unroll
                for (int j = 0; j < 8; j++)
                    acc[i][j] = fmaf(ra[i], rb[j], acc[i][j]);
        }
        __syncthreads();
    }

    // Write C tile
#pragma unroll
    for (int i = 0; i < 8; i++) {
        float* crow = C + (size_t)(bm + ty * 8 + i) * N_DIM + bn + tx * 8;
        *(float4*)(crow + 0) = *(float4*)&acc[i][0];
        *(float4*)(crow + 4) = *(float4*)&acc[i][4];
    }
}

// -------------------------------------------------------------------------
// Per-row exact top-K threshold (4-pass MSD radix select on monotonic keys),
// then encoded = relu(v) * (v >= thr), normalized by row L2 norm. In place.
// One block (256 threads) per row; 16 elements per thread.
// -------------------------------------------------------------------------
__device__ __forceinline__ unsigned float_to_key(float f) {
    unsigned u = __float_as_uint(f);
    return (u & 0x80000000u) ? ~u : (u | 0x80000000u);
}
__device__ __forceinline__ float key_to_float(unsigned k) {
    unsigned u = (k & 0x80000000u) ? (k ^ 0x80000000u) : ~k;
    return __uint_as_float(u);
}

__global__ void __launch_bounds__(256)
select_normalize_kernel(float* __restrict__ data) {
    const int row = blockIdx.x;
    float* rowp = data + (size_t)row * N_DIM;
    float4* rp4 = (float4*)rowp;

    __shared__ unsigned hist[256];
    __shared__ unsigned s_prefix, s_remaining;
    __shared__ float s_warpsum[8];
    __shared__ float s_inv;

    const int tid = threadIdx.x;

    float v[16];
    unsigned key[16];
#pragma unroll
    for (int i = 0; i < 4; i++) {
        float4 f = rp4[tid + 256 * i];
        v[i * 4 + 0] = f.x; v[i * 4 + 1] = f.y;
        v[i * 4 + 2] = f.z; v[i * 4 + 3] = f.w;
    }
#pragma unroll
    for (int i = 0; i < 16; i++) key[i] = float_to_key(v[i]);

    unsigned prefix = 0;
    unsigned remaining = TOPK;

#pragma unroll
    for (int pass = 3; pass >= 0; pass--) {
        const int shift = pass * 8;
        // bits strictly above the current byte
        const unsigned mask_hi = (pass == 3) ? 0u : ~((1u << (shift + 8)) - 1u);

        hist[tid] = 0;
        __syncthreads();

#pragma unroll
        for (int i = 0; i < 16; i++) {
            if ((key[i] & mask_hi) == prefix)
                atomicAdd(&hist[(key[i] >> shift) & 255u], 1u);
        }
        __syncthreads();

        if (tid == 0) {
            unsigned cum = 0;
            for (int b = 255; b >= 0; b--) {
                cum += hist[b];
                if (cum >= remaining) {
                    s_prefix = prefix | ((unsigned)b << shift);
                    s_remaining = remaining - (cum - hist[b]);
                    break;
                }
            }
        }
        __syncthreads();
        prefix = s_prefix;
        remaining = s_remaining;
        __syncthreads();
    }

    const float thr = key_to_float(prefix);

    float e[16];
    float sum = 0.f;
#pragma unroll
    for (int i = 0; i < 16; i++) {
        float ev = (v[i] >= thr) ? fmaxf(v[i], 0.f) : 0.f;
        e[i] = ev;
        sum = fmaf(ev, ev, sum);
    }

    // block reduce
#pragma unroll
    for (int off = 16; off >= 1; off >>= 1)
        sum += __shfl_xor_sync(0xFFFFFFFFu, sum, off);
    if ((tid & 31) == 0) s_warpsum[tid >> 5] = sum;
    __syncthreads();
    if (tid == 0) {
        float t = 0.f;
#pragma unroll
        for (int w = 0; w < 8; w++) t += s_warpsum[w];
        float norm = sqrtf(t);
        s_inv = 1.0f / fmaxf(norm, 1e-12f);
    }
    __syncthreads();
    const float inv = s_inv;

#pragma unroll
    for (int i = 0; i < 4; i++) {
        float4 f;
        f.x = e[i * 4 + 0] * inv; f.y = e[i * 4 + 1] * inv;
        f.z = e[i * 4 + 2] * inv; f.w = e[i * 4 + 3] * inv;
        rp4[tid + 256 * i] = f;
    }
}

// -------------------------------------------------------------------------
// Launch
// -------------------------------------------------------------------------
extern "C" void kernel_launch(void* const* d_in, const int* in_sizes, int n_in,
                              void* d_out, int out_size) {
    const float* x = (const float*)d_in[0];                 // [16384, 1024]
    const float* w = (const float*)d_in[1];                 // [4096, 1024]
    float* out = (float*)d_out;                             // [16384, 4096]

    init_flags_kernel<<<1, 1>>>();
    scan_neg_kernel<<<256, 256>>>((const float4*)x, (M_DIM * K_DIM) / 4);

    dim3 grid(N_DIM / BN, M_DIM / BM);
    gemm_kernel<<<grid, 256>>>(x, w, out);

    select_normalize_kernel<<<M_DIM, 256>>>(out);
}

// round 3
// speedup vs baseline: 1.9090x; 1.9090x over previous
#include <cuda_runtime.h>
#include <cstdint>

#define M_DIM 16384
#define N_DIM 4096
#define K_DIM 1024
#define TOPK  409

// ---------------------------------------------------------------------------
// Device scratch (no allocations allowed -> __device__ globals)
// ---------------------------------------------------------------------------
__device__ int   g_has_neg;
__device__ float g_S[N_DIM];                                  // row sums of W
__device__ float g_xa[(size_t)M_DIM * K_DIM];                 // tf32-rounded x
__device__ float g_wa[(size_t)N_DIM * K_DIM];                 // tf32-rounded W

// ---------------------------------------------------------------------------
// K1: flags + negative scan
// ---------------------------------------------------------------------------
__global__ void init_flags_kernel() { g_has_neg = 0; }

__global__ void scan_neg_kernel(const float4* __restrict__ x, int n4) {
    int idx = blockIdx.x * blockDim.x + threadIdx.x;
    int stride = gridDim.x * blockDim.x;
    for (int i = idx; i < n4; i += stride) {
        float4 v = x[i];
        if (v.x < 0.f || v.y < 0.f || v.z < 0.f || v.w < 0.f) { g_has_neg = 1; break; }
    }
}

// ---------------------------------------------------------------------------
// K2: row sums of W (for bipolar affine fixup)
// ---------------------------------------------------------------------------
__global__ void __launch_bounds__(128)
rowsum_kernel(const float* __restrict__ Wm) {
    __shared__ float ws[4];
    const int n = blockIdx.x;
    float s = 0.f;
    for (int k = threadIdx.x; k < K_DIM; k += 128)
        s += Wm[(size_t)n * K_DIM + k];
#pragma unroll
    for (int off = 16; off >= 1; off >>= 1)
        s += __shfl_xor_sync(0xFFFFFFFFu, s, off);
    if ((threadIdx.x & 31) == 0) ws[threadIdx.x >> 5] = s;
    __syncthreads();
    if (threadIdx.x == 0) g_S[n] = ws[0] + ws[1] + ws[2] + ws[3];
}

// ---------------------------------------------------------------------------
// K3: round-to-nearest tf32 conversion (removes in-MMA truncation bias)
// ---------------------------------------------------------------------------
__device__ __forceinline__ float to_tf32(float f) {
    uint32_t r;
    asm("cvt.rna.tf32.f32 %0, %1;" : "=r"(r) : "f"(f));
    return __uint_as_float(r);
}

__global__ void __launch_bounds__(256)
conv_x_kernel(const float4* __restrict__ src) {
    float4* dst = (float4*)g_xa;
    const int n4 = (M_DIM * K_DIM) / 4;
    for (int i = blockIdx.x * blockDim.x + threadIdx.x; i < n4;
         i += gridDim.x * blockDim.x) {
        float4 v = src[i];
        v.x = to_tf32(v.x); v.y = to_tf32(v.y);
        v.z = to_tf32(v.z); v.w = to_tf32(v.w);
        dst[i] = v;
    }
}

__global__ void __launch_bounds__(256)
conv_w_kernel(const float4* __restrict__ src) {
    float4* dst = (float4*)g_wa;
    const int n4 = (N_DIM * K_DIM) / 4;
    for (int i = blockIdx.x * blockDim.x + threadIdx.x; i < n4;
         i += gridDim.x * blockDim.x) {
        float4 v = src[i];
        v.x = to_tf32(v.x); v.y = to_tf32(v.y);
        v.z = to_tf32(v.z); v.w = to_tf32(v.w);
        dst[i] = v;
    }
}

// ---------------------------------------------------------------------------
// K4: TF32 mma.sync GEMM  P[M,N] = xa[M,K] * wa[N,K]^T
// 128x128x32 CTA tile, 3-stage cp.async pipeline, 8 warps (64x32 warp tiles)
// ---------------------------------------------------------------------------
#define BK 32
#define STRIDE 36                      // floats per smem row (pad kills conflicts)
#define NSTAGES 3
#define GCHUNKS (K_DIM / BK)           // 32
#define STAGE_FLOATS (2 * 128 * STRIDE)  // A tile + B tile = 9216 floats

#define CPA16(dst, src) \
    asm volatile("cp.async.cg.shared.global [%0], [%1], 16;" :: "r"(dst), "l"(src) : "memory")
#define CPA_COMMIT() asm volatile("cp.async.commit_group;" ::: "memory")
#define CPA_WAIT1()  asm volatile("cp.async.wait_group 1;" ::: "memory")

__device__ __forceinline__ uint32_t smem_u32(const void* p) {
    uint32_t a;
    asm("{ .reg .u64 t; cvta.to.shared.u64 t, %1; cvt.u32.u64 %0, t; }"
        : "=r"(a) : "l"(p));
    return a;
}

__device__ __forceinline__ void mma_tf32(float c[4], const uint32_t a[4],
                                         const uint32_t b[2]) {
    asm volatile(
        "mma.sync.aligned.m16n8k8.row.col.f32.tf32.tf32.f32 "
        "{%0,%1,%2,%3}, {%4,%5,%6,%7}, {%8,%9}, {%0,%1,%2,%3};"
        : "+f"(c[0]), "+f"(c[1]), "+f"(c[2]), "+f"(c[3])
        : "r"(a[0]), "r"(a[1]), "r"(a[2]), "r"(a[3]), "r"(b[0]), "r"(b[1]));
}

__global__ void __launch_bounds__(256, 2)
gemm_mma_kernel(float* __restrict__ C) {
    extern __shared__ float smem[];

    const int tid  = threadIdx.x;
    const int wid  = tid >> 5;
    const int lane = tid & 31;
    const int g = lane >> 2;     // group id
    const int t = lane & 3;      // thread in group
    const int bm = blockIdx.y * 128;
    const int bn = blockIdx.x * 128;

    const int warp_m = (wid & 1) * 64;
    const int warp_n = (wid >> 1) * 32;

    // cp.async loader mapping: each thread copies 4x16B for A and 4x16B for B
    const int lrow  = tid >> 1;          // 0..127
    const int lhalf = (tid & 1) * 16;    // float offset 0 or 16 within BK=32 row

    const float* Ag = g_xa + (size_t)(bm + lrow) * K_DIM + lhalf;
    const float* Bg = g_wa + (size_t)(bn + lrow) * K_DIM + lhalf;

    uint32_t sA_base[NSTAGES], sB_base[NSTAGES];
#pragma unroll
    for (int s = 0; s < NSTAGES; s++) {
        sA_base[s] = smem_u32(&smem[s * STAGE_FLOATS + lrow * STRIDE + lhalf]);
        sB_base[s] = smem_u32(&smem[s * STAGE_FLOATS + 128 * STRIDE + lrow * STRIDE + lhalf]);
    }

    float acc[4][4][4];
#pragma unroll
    for (int i = 0; i < 4; i++)
#pragma unroll
        for (int j = 0; j < 4; j++)
#pragma unroll
            for (int q = 0; q < 4; q++) acc[i][j][q] = 0.f;

    // issue one stage of copies
    auto issue = [&](int c, int s) {
#pragma unroll
        for (int q = 0; q < 4; q++)
            CPA16(sA_base[s] + q * 16, Ag + (size_t)c * BK + q * 4);
#pragma unroll
        for (int q = 0; q < 4; q++)
            CPA16(sB_base[s] + q * 16, Bg + (size_t)c * BK + q * 4);
    };

    issue(0, 0); CPA_COMMIT();
    issue(1, 1); CPA_COMMIT();

    for (int c = 0; c < GCHUNKS; ++c) {
        CPA_WAIT1();
        __syncthreads();

        const int cn = c + 2;
        if (cn < GCHUNKS) issue(cn, cn % NSTAGES);
        CPA_COMMIT();

        const uint32_t* As = (const uint32_t*)&smem[(c % NSTAGES) * STAGE_FLOATS];
        const uint32_t* Bs = As + 128 * STRIDE;

#pragma unroll
        for (int ks = 0; ks < 4; ++ks) {
            uint32_t a[4][4], b[4][2];
#pragma unroll
            for (int i = 0; i < 4; i++) {
                const int m = warp_m + i * 16 + g;
                a[i][0] = As[m * STRIDE + ks * 8 + t];
                a[i][1] = As[(m + 8) * STRIDE + ks * 8 + t];
                a[i][2] = As[m * STRIDE + ks * 8 + t + 4];
                a[i][3] = As[(m + 8) * STRIDE + ks * 8 + t + 4];
            }
#pragma unroll
            for (int j = 0; j < 4; j++) {
                const int n = warp_n + j * 8 + g;
                b[j][0] = Bs[n * STRIDE + ks * 8 + t];
                b[j][1] = Bs[n * STRIDE + ks * 8 + t + 4];
            }
#pragma unroll
            for (int i = 0; i < 4; i++)
#pragma unroll
                for (int j = 0; j < 4; j++)
                    mma_tf32(acc[i][j], a[i], b[j]);
        }
    }

    // epilogue: float2 stores (32B-sector aligned groups)
#pragma unroll
    for (int i = 0; i < 4; i++) {
#pragma unroll
        for (int j = 0; j < 4; j++) {
            const int r0 = bm + warp_m + i * 16 + g;
            const int cc = bn + warp_n + j * 8 + 2 * t;
            float2 v0 = {acc[i][j][0], acc[i][j][1]};
            float2 v1 = {acc[i][j][2], acc[i][j][3]};
            *(float2*)(C + (size_t)r0 * N_DIM + cc) = v0;
            *(float2*)(C + (size_t)(r0 + 8) * N_DIM + cc) = v1;
        }
    }
}

// ---------------------------------------------------------------------------
// K5: per-row exact top-K with approximate-GEMM fixup, then normalize.
// ---------------------------------------------------------------------------
__device__ __forceinline__ unsigned float_to_key(float f) {
    unsigned u = __float_as_uint(f);
    return (u & 0x80000000u) ? ~u : (u | 0x80000000u);
}
__device__ __forceinline__ float key_to_float(unsigned k) {
    unsigned u = (k & 0x80000000u) ? (k ^ 0x80000000u) : ~k;
    return __uint_as_float(u);
}

#define CAND_CAP 128
#define FIXW 0.01f

__global__ void __launch_bounds__(256)
fixup_kernel(float* __restrict__ P, const float* __restrict__ X,
             const float* __restrict__ Wm, float* __restrict__ out) {
    __shared__ float    s_row[N_DIM];
    __shared__ float    s_xs[K_DIM];
    __shared__ unsigned char s_mask[N_DIM];
    __shared__ unsigned hist[256];
    __shared__ unsigned s_prefix, s_remaining;
    __shared__ int      s_cnt, s_nc;
    __shared__ int      s_cidx[CAND_CAP];
    __shared__ float    s_cval[CAND_CAP];
    __shared__ float    s_wsum[8];
    __shared__ float    s_inv;

    const int row = blockIdx.x;
    const int tid = threadIdx.x;
    const bool bip = (g_has_neg == 0);

    const float4* p4 = (const float4*)(P + (size_t)row * N_DIM);

    float v[16];
#pragma unroll
    for (int i = 0; i < 4; i++) {
        float4 f = p4[tid + 256 * i];
        const int cb = (tid + 256 * i) * 4;
        if (bip) {
            f.x = 2.f * f.x - g_S[cb + 0];
            f.y = 2.f * f.y - g_S[cb + 1];
            f.z = 2.f * f.z - g_S[cb + 2];
            f.w = 2.f * f.w - g_S[cb + 3];
        }
        v[i * 4 + 0] = f.x; v[i * 4 + 1] = f.y;
        v[i * 4 + 2] = f.z; v[i * 4 + 3] = f.w;
        s_row[cb + 0] = f.x; s_row[cb + 1] = f.y;
        s_row[cb + 2] = f.z; s_row[cb + 3] = f.w;
    }

    unsigned key[16];
#pragma unroll
    for (int i = 0; i < 16; i++) key[i] = float_to_key(v[i]);

    // 4-pass MSD radix select on approximate values
    unsigned prefix = 0, remaining = TOPK;
#pragma unroll
    for (int pass = 3; pass >= 0; pass--) {
        const int shift = pass * 8;
        const unsigned mask_hi = (pass == 3) ? 0u : ~((1u << (shift + 8)) - 1u);
        hist[tid] = 0;
        __syncthreads();
#pragma unroll
        for (int i = 0; i < 16; i++) {
            if ((key[i] & mask_hi) == prefix)
                atomicAdd(&hist[(key[i] >> shift) & 255u], 1u);
        }
        __syncthreads();
        if (tid == 0) {
            unsigned cum = 0;
            for (int b = 255; b >= 0; b--) {
                cum += hist[b];
                if (cum >= remaining) {
                    s_prefix = prefix | ((unsigned)b << shift);
                    s_remaining = remaining - (cum - hist[b]);
                    break;
                }
            }
        }
        __syncthreads();
        prefix = s_prefix;
        remaining = s_remaining;
        __syncthreads();
    }
    const float thr = key_to_float(prefix);

    if (tid == 0) { s_cnt = 0; s_nc = 0; }
    __syncthreads();

    const float hi = thr + FIXW, lo = thr - FIXW;
    int myin = 0;
#pragma unroll
    for (int i = 0; i < 16; i++) {
        const int col = (tid + 256 * (i >> 2)) * 4 + (i & 3);
        const float val = v[i];
        const bool sure = (val > hi);
        s_mask[col] = sure ? 1 : 0;
        myin += sure ? 1 : 0;
        if (val <= hi && val >= lo) {
            int slot = atomicAdd(&s_nc, 1);
            if (slot < CAND_CAP) s_cidx[slot] = col;
        }
    }
    atomicAdd(&s_cnt, myin);

    for (int k = tid; k < K_DIM; k += 256) {
        float xv = X[(size_t)row * K_DIM + k];
        s_xs[k] = bip ? (xv - 0.5f) * 2.0f : xv;
    }
    __syncthreads();

    const int n_sure = s_cnt;
    const int n_c = min(s_nc, CAND_CAP);
    int need = TOPK - n_sure;
    if (need < 0) need = 0;
    if (need > n_c) need = n_c;

    // exact fp32 dots for candidates (one warp per candidate)
    const int wid = tid >> 5, lid = tid & 31;
    for (int j = wid; j < n_c; j += 8) {
        const int col = s_cidx[j];
        const float* wr = Wm + (size_t)col * K_DIM;
        float accv = 0.f;
#pragma unroll
        for (int i = 0; i < 32; i++) {
            const int k = lid + i * 32;
            accv = fmaf(s_xs[k], wr[k], accv);
        }
#pragma unroll
        for (int off = 16; off >= 1; off >>= 1)
            accv += __shfl_xor_sync(0xFFFFFFFFu, accv, off);
        if (lid == 0) {
            s_cval[j] = accv;
            s_row[col] = accv;
        }
    }
    __syncthreads();

    if (tid < n_c) {
        const float vt = s_cval[tid];
        int rank = 0;
        for (int k = 0; k < n_c; k++) {
            const float vk = s_cval[k];
            rank += (vk > vt || (vk == vt && k < tid)) ? 1 : 0;
        }
        s_mask[s_cidx[tid]] = (rank < need) ? 1 : 0;
    }
    __syncthreads();

    // encode + normalize
    float e[16];
    float ss = 0.f;
#pragma unroll
    for (int i = 0; i < 16; i++) {
        const int col = (tid + 256 * (i >> 2)) * 4 + (i & 3);
        const float val = s_row[col];
        const float ev = s_mask[col] ? fmaxf(val, 0.f) : 0.f;
        e[i] = ev;
        ss = fmaf(ev, ev, ss);
    }
#pragma unroll
    for (int off = 16; off >= 1; off >>= 1)
        ss += __shfl_xor_sync(0xFFFFFFFFu, ss, off);
    if (lid == 0) s_wsum[wid] = ss;
    __syncthreads();
    if (tid == 0) {
        float tt = 0.f;
#pragma unroll
        for (int w = 0; w < 8; w++) tt += s_wsum[w];
        s_inv = 1.0f / fmaxf(sqrtf(tt), 1e-12f);
    }
    __syncthreads();
    const float inv = s_inv;

    float4* o4 = (float4*)(out + (size_t)row * N_DIM);
#pragma unroll
    for (int i = 0; i < 4; i++) {
        float4 f;
        f.x = e[i * 4 + 0] * inv; f.y = e[i * 4 + 1] * inv;
        f.z = e[i * 4 + 2] * inv; f.w = e[i * 4 + 3] * inv;
        o4[tid + 256 * i] = f;
    }
}

// ---------------------------------------------------------------------------
// Launch
// ---------------------------------------------------------------------------
extern "C" void kernel_launch(void* const* d_in, const int* in_sizes, int n_in,
                              void* d_out, int out_size) {
    const float* x = (const float*)d_in[0];   // [16384, 1024]
    const float* w = (const float*)d_in[1];   // [4096, 1024]
    float* out = (float*)d_out;               // [16384, 4096]

    const int smem_bytes = NSTAGES * STAGE_FLOATS * sizeof(float);
    cudaFuncSetAttribute(gemm_mma_kernel,
                         cudaFuncAttributeMaxDynamicSharedMemorySize, smem_bytes);

    init_flags_kernel<<<1, 1>>>();
    scan_neg_kernel<<<256, 256>>>((const float4*)x, (M_DIM * K_DIM) / 4);
    rowsum_kernel<<<N_DIM, 128>>>(w);
    conv_x_kernel<<<2048, 256>>>((const float4*)x);
    conv_w_kernel<<<1024, 256>>>((const float4*)w);

    dim3 ggrid(N_DIM / 128, M_DIM / 128);
    gemm_mma_kernel<<<ggrid, 256, smem_bytes>>>(out);

    fixup_kernel<<<M_DIM, 256>>>(out, x, w, out);
}

// round 4
// speedup vs baseline: 3.3838x; 1.7725x over previous
#include <cuda_runtime.h>
#include <cuda_fp16.h>
#include <cstdint>

#define M_DIM 16384
#define N_DIM 4096
#define K_DIM 1024
#define TOPK  409

// ---------------------------------------------------------------------------
// Device scratch
// ---------------------------------------------------------------------------
__device__ int    g_has_neg;
__device__ float  g_S[N_DIM];                                // row sums of W
__device__ __half g_xh[(size_t)M_DIM * K_DIM];               // fp16 x
__device__ __half g_wh[(size_t)N_DIM * K_DIM];               // fp16 W

// ---------------------------------------------------------------------------
// K1: flags + negative scan
// ---------------------------------------------------------------------------
__global__ void init_flags_kernel() { g_has_neg = 0; }

__global__ void scan_neg_kernel(const float4* __restrict__ x, int n4) {
    int idx = blockIdx.x * blockDim.x + threadIdx.x;
    int stride = gridDim.x * blockDim.x;
    for (int i = idx; i < n4; i += stride) {
        float4 v = x[i];
        if (v.x < 0.f || v.y < 0.f || v.z < 0.f || v.w < 0.f) { g_has_neg = 1; break; }
    }
}

// ---------------------------------------------------------------------------
// K2: row sums of W (for bipolar affine fixup)
// ---------------------------------------------------------------------------
__global__ void __launch_bounds__(128)
rowsum_kernel(const float* __restrict__ Wm) {
    __shared__ float ws[4];
    const int n = blockIdx.x;
    float s = 0.f;
    for (int k = threadIdx.x; k < K_DIM; k += 128)
        s += Wm[(size_t)n * K_DIM + k];
#pragma unroll
    for (int off = 16; off >= 1; off >>= 1)
        s += __shfl_xor_sync(0xFFFFFFFFu, s, off);
    if ((threadIdx.x & 31) == 0) ws[threadIdx.x >> 5] = s;
    __syncthreads();
    if (threadIdx.x == 0) g_S[n] = ws[0] + ws[1] + ws[2] + ws[3];
}

// ---------------------------------------------------------------------------
// K3: fp32 -> fp16 conversion (RN; same mantissa budget as tf32-rna)
// ---------------------------------------------------------------------------
__global__ void __launch_bounds__(256)
conv_x_kernel(const float4* __restrict__ src) {
    uint2* dst = (uint2*)g_xh;
    const int n4 = (M_DIM * K_DIM) / 4;
    for (int i = blockIdx.x * blockDim.x + threadIdx.x; i < n4;
         i += gridDim.x * blockDim.x) {
        float4 v = src[i];
        __half2 h01 = __floats2half2_rn(v.x, v.y);
        __half2 h23 = __floats2half2_rn(v.z, v.w);
        uint2 u;
        u.x = *(uint32_t*)&h01;
        u.y = *(uint32_t*)&h23;
        dst[i] = u;
    }
}

__global__ void __launch_bounds__(256)
conv_w_kernel(const float4* __restrict__ src) {
    uint2* dst = (uint2*)g_wh;
    const int n4 = (N_DIM * K_DIM) / 4;
    for (int i = blockIdx.x * blockDim.x + threadIdx.x; i < n4;
         i += gridDim.x * blockDim.x) {
        float4 v = src[i];
        __half2 h01 = __floats2half2_rn(v.x, v.y);
        __half2 h23 = __floats2half2_rn(v.z, v.w);
        uint2 u;
        u.x = *(uint32_t*)&h01;
        u.y = *(uint32_t*)&h23;
        dst[i] = u;
    }
}

// ---------------------------------------------------------------------------
// K4: fp16 mma.sync GEMM  P[M,N] = xh[M,K] * wh[N,K]^T   (fp32 accumulate)
// 128x128x32 CTA tile, 3-stage cp.async pipeline, 8 warps (64x32 warp tiles)
// smem rows padded to 80B -> conflict-free ldmatrix (banks 20*i mod 32)
// ---------------------------------------------------------------------------
#define BKH 32                          // halves per k-chunk
#define ROWB 80                         // bytes per padded smem row
#define NSTAGES 3
#define GCHUNKS (K_DIM / BKH)           // 32
#define ATILE_B (128 * ROWB)            // 10240 B
#define STAGE_B (2 * ATILE_B)           // 20480 B

#define CPA16(dst, src) \
    asm volatile("cp.async.cg.shared.global [%0], [%1], 16;" :: "r"(dst), "l"(src) : "memory")
#define CPA_COMMIT() asm volatile("cp.async.commit_group;" ::: "memory")
#define CPA_WAIT1()  asm volatile("cp.async.wait_group 1;" ::: "memory")

__device__ __forceinline__ uint32_t smem_u32(const void* p) {
    uint32_t a;
    asm("{ .reg .u64 t; cvta.to.shared.u64 t, %1; cvt.u32.u64 %0, t; }"
        : "=r"(a) : "l"(p));
    return a;
}

__device__ __forceinline__ void ldmx4(uint32_t r[4], uint32_t addr) {
    asm volatile("ldmatrix.sync.aligned.m8n8.x4.shared.b16 {%0,%1,%2,%3}, [%4];"
                 : "=r"(r[0]), "=r"(r[1]), "=r"(r[2]), "=r"(r[3]) : "r"(addr));
}

__device__ __forceinline__ void mma_f16(float c[4], const uint32_t a[4],
                                        const uint32_t b0, const uint32_t b1) {
    asm volatile(
        "mma.sync.aligned.m16n8k16.row.col.f32.f16.f16.f32 "
        "{%0,%1,%2,%3}, {%4,%5,%6,%7}, {%8,%9}, {%0,%1,%2,%3};"
        : "+f"(c[0]), "+f"(c[1]), "+f"(c[2]), "+f"(c[3])
        : "r"(a[0]), "r"(a[1]), "r"(a[2]), "r"(a[3]), "r"(b0), "r"(b1));
}

__global__ void __launch_bounds__(256, 2)
gemm_f16_kernel(float* __restrict__ C) {
    extern __shared__ char smem[];
    const uint32_t sbase = smem_u32(smem);

    const int tid  = threadIdx.x;
    const int wid  = tid >> 5;
    const int lane = tid & 31;
    const int g = lane >> 2;
    const int t = lane & 3;
    const int bm = blockIdx.y * 128;
    const int bn = blockIdx.x * 128;

    const int warp_m = (wid & 1) * 64;
    const int warp_n = (wid >> 1) * 32;

    // ---- cp.async loader mapping: 512 16B-segments per tile, 2 per thread ----
    // seg = tid + 256*q; row = seg>>2; c16 = seg&3
    const __half* Agbase = g_xh + (size_t)bm * K_DIM;
    const __half* Bgbase = g_wh + (size_t)bn * K_DIM;

    // ---- ldmatrix per-lane addressing ----
    const int j8   = lane & 7;
    const int quad = lane >> 3;
    // A tiles: quad0:(rows 0-7,k0-7) quad1:(rows8-15,k0-7) quad2:(rows0-7,k8-15) quad3:(rows8-15,k8-15)
    const int arow  = warp_m + ((quad & 1) << 3) + j8;
    const int akoff = (quad & 2) ? 16 : 0;              // bytes
    // B tiles: quad0:(n0-7,k0-7) quad1:(n0-7,k8-15) quad2:(n8-15,k0-7) quad3:(n8-15,k8-15)
    const int brow  = warp_n + ((quad & 2) << 2) + j8;
    const int bkoff = (quad & 1) ? 16 : 0;

    uint32_t aoff[4], boff[2];
#pragma unroll
    for (int i = 0; i < 4; i++) aoff[i] = (uint32_t)((arow + i * 16) * ROWB + akoff);
#pragma unroll
    for (int jt = 0; jt < 2; jt++) boff[jt] = (uint32_t)((brow + jt * 16) * ROWB + bkoff);

    float acc[4][4][4];
#pragma unroll
    for (int i = 0; i < 4; i++)
#pragma unroll
        for (int j = 0; j < 4; j++)
#pragma unroll
            for (int q = 0; q < 4; q++) acc[i][j][q] = 0.f;

    auto issue = [&](int c, int s) {
        const uint32_t stA = sbase + s * STAGE_B;
        const uint32_t stB = stA + ATILE_B;
#pragma unroll
        for (int q = 0; q < 2; q++) {
            const int seg = tid + 256 * q;
            const int row = seg >> 2;
            const int c16 = seg & 3;
            const uint32_t doff = (uint32_t)(row * ROWB + c16 * 16);
            CPA16(stA + doff, Agbase + (size_t)row * K_DIM + c * BKH + c16 * 8);
            CPA16(stB + doff, Bgbase + (size_t)row * K_DIM + c * BKH + c16 * 8);
        }
    };

    issue(0, 0); CPA_COMMIT();
    issue(1, 1); CPA_COMMIT();

    for (int c = 0; c < GCHUNKS; ++c) {
        CPA_WAIT1();
        __syncthreads();

        const int cn = c + 2;
        if (cn < GCHUNKS) issue(cn, cn % NSTAGES);
        CPA_COMMIT();

        const uint32_t stA = sbase + (c % NSTAGES) * STAGE_B;
        const uint32_t stB = stA + ATILE_B;

#pragma unroll
        for (int ks = 0; ks < 2; ++ks) {
            uint32_t a[4][4], b[2][4];
#pragma unroll
            for (int i = 0; i < 4; i++)
                ldmx4(a[i], stA + aoff[i] + ks * 32);
#pragma unroll
            for (int jt = 0; jt < 2; jt++)
                ldmx4(b[jt], stB + boff[jt] + ks * 32);
#pragma unroll
            for (int i = 0; i < 4; i++) {
                mma_f16(acc[i][0], a[i], b[0][0], b[0][1]);
                mma_f16(acc[i][1], a[i], b[0][2], b[0][3]);
                mma_f16(acc[i][2], a[i], b[1][0], b[1][1]);
                mma_f16(acc[i][3], a[i], b[1][2], b[1][3]);
            }
        }
        __syncthreads();
    }

    // epilogue
#pragma unroll
    for (int i = 0; i < 4; i++) {
#pragma unroll
        for (int j = 0; j < 4; j++) {
            const int r0 = bm + warp_m + i * 16 + g;
            const int cc = bn + warp_n + j * 8 + 2 * t;
            float2 v0 = {acc[i][j][0], acc[i][j][1]};
            float2 v1 = {acc[i][j][2], acc[i][j][3]};
            *(float2*)(C + (size_t)r0 * N_DIM + cc) = v0;
            *(float2*)(C + (size_t)(r0 + 8) * N_DIM + cc) = v1;
        }
    }
}

// ---------------------------------------------------------------------------
// K5: per-row exact top-K with approximate-GEMM fixup, then normalize.
// ---------------------------------------------------------------------------
__device__ __forceinline__ unsigned float_to_key(float f) {
    unsigned u = __float_as_uint(f);
    return (u & 0x80000000u) ? ~u : (u | 0x80000000u);
}
__device__ __forceinline__ float key_to_float(unsigned k) {
    unsigned u = (k & 0x80000000u) ? (k ^ 0x80000000u) : ~k;
    return __uint_as_float(u);
}

#define CAND_CAP 128
#define FIXW 0.01f

__global__ void __launch_bounds__(256)
fixup_kernel(float* __restrict__ P, const float* __restrict__ X,
             const float* __restrict__ Wm, float* __restrict__ out) {
    __shared__ float    s_row[N_DIM];
    __shared__ float    s_xs[K_DIM];
    __shared__ unsigned char s_mask[N_DIM];
    __shared__ unsigned hist[256];
    __shared__ unsigned s_prefix, s_remaining;
    __shared__ int      s_cnt, s_nc;
    __shared__ int      s_cidx[CAND_CAP];
    __shared__ float    s_cval[CAND_CAP];
    __shared__ float    s_wsum[8];
    __shared__ float    s_inv;

    const int row = blockIdx.x;
    const int tid = threadIdx.x;
    const bool bip = (g_has_neg == 0);

    const float4* p4 = (const float4*)(P + (size_t)row * N_DIM);

    float v[16];
#pragma unroll
    for (int i = 0; i < 4; i++) {
        float4 f = p4[tid + 256 * i];
        const int cb = (tid + 256 * i) * 4;
        if (bip) {
            f.x = 2.f * f.x - g_S[cb + 0];
            f.y = 2.f * f.y - g_S[cb + 1];
            f.z = 2.f * f.z - g_S[cb + 2];
            f.w = 2.f * f.w - g_S[cb + 3];
        }
        v[i * 4 + 0] = f.x; v[i * 4 + 1] = f.y;
        v[i * 4 + 2] = f.z; v[i * 4 + 3] = f.w;
        s_row[cb + 0] = f.x; s_row[cb + 1] = f.y;
        s_row[cb + 2] = f.z; s_row[cb + 3] = f.w;
    }

    unsigned key[16];
#pragma unroll
    for (int i = 0; i < 16; i++) key[i] = float_to_key(v[i]);

    unsigned prefix = 0, remaining = TOPK;
#pragma unroll
    for (int pass = 3; pass >= 0; pass--) {
        const int shift = pass * 8;
        const unsigned mask_hi = (pass == 3) ? 0u : ~((1u << (shift + 8)) - 1u);
        hist[tid] = 0;
        __syncthreads();
#pragma unroll
        for (int i = 0; i < 16; i++) {
            if ((key[i] & mask_hi) == prefix)
                atomicAdd(&hist[(key[i] >> shift) & 255u], 1u);
        }
        __syncthreads();
        if (tid == 0) {
            unsigned cum = 0;
            for (int b = 255; b >= 0; b--) {
                cum += hist[b];
                if (cum >= remaining) {
                    s_prefix = prefix | ((unsigned)b << shift);
                    s_remaining = remaining - (cum - hist[b]);
                    break;
                }
            }
        }
        __syncthreads();
        prefix = s_prefix;
        remaining = s_remaining;
        __syncthreads();
    }
    const float thr = key_to_float(prefix);

    if (tid == 0) { s_cnt = 0; s_nc = 0; }
    __syncthreads();

    const float hi = thr + FIXW, lo = thr - FIXW;
    int myin = 0;
#pragma unroll
    for (int i = 0; i < 16; i++) {
        const int col = (tid + 256 * (i >> 2)) * 4 + (i & 3);
        const float val = v[i];
        const bool sure = (val > hi);
        s_mask[col] = sure ? 1 : 0;
        myin += sure ? 1 : 0;
        if (val <= hi && val >= lo) {
            int slot = atomicAdd(&s_nc, 1);
            if (slot < CAND_CAP) s_cidx[slot] = col;
        }
    }
    atomicAdd(&s_cnt, myin);

    for (int k = tid; k < K_DIM; k += 256) {
        float xv = X[(size_t)row * K_DIM + k];
        s_xs[k] = bip ? (xv - 0.5f) * 2.0f : xv;
    }
    __syncthreads();

    const int n_sure = s_cnt;
    const int n_c = min(s_nc, CAND_CAP);
    int need = TOPK - n_sure;
    if (need < 0) need = 0;
    if (need > n_c) need = n_c;

    const int wid = tid >> 5, lid = tid & 31;
    for (int j = wid; j < n_c; j += 8) {
        const int col = s_cidx[j];
        const float* wr = Wm + (size_t)col * K_DIM;
        float accv = 0.f;
#pragma unroll
        for (int i = 0; i < 32; i++) {
            const int k = lid + i * 32;
            accv = fmaf(s_xs[k], wr[k], accv);
        }
#pragma unroll
        for (int off = 16; off >= 1; off >>= 1)
            accv += __shfl_xor_sync(0xFFFFFFFFu, accv, off);
        if (lid == 0) {
            s_cval[j] = accv;
            s_row[col] = accv;
        }
    }
    __syncthreads();

    if (tid < n_c) {
        const float vt = s_cval[tid];
        int rank = 0;
        for (int k = 0; k < n_c; k++) {
            const float vk = s_cval[k];
            rank += (vk > vt || (vk == vt && k < tid)) ? 1 : 0;
        }
        s_mask[s_cidx[tid]] = (rank < need) ? 1 : 0;
    }
    __syncthreads();

    float e[16];
    float ss = 0.f;
#pragma unroll
    for (int i = 0; i < 16; i++) {
        const int col = (tid + 256 * (i >> 2)) * 4 + (i & 3);
        const float val = s_row[col];
        const float ev = s_mask[col] ? fmaxf(val, 0.f) : 0.f;
        e[i] = ev;
        ss = fmaf(ev, ev, ss);
    }
#pragma unroll
    for (int off = 16; off >= 1; off >>= 1)
        ss += __shfl_xor_sync(0xFFFFFFFFu, ss, off);
    if (lid == 0) s_wsum[wid] = ss;
    __syncthreads();
    if (tid == 0) {
        float tt = 0.f;
#pragma unroll
        for (int w = 0; w < 8; w++) tt += s_wsum[w];
        s_inv = 1.0f / fmaxf(sqrtf(tt), 1e-12f);
    }
    __syncthreads();
    const float inv = s_inv;

    float4* o4 = (float4*)(out + (size_t)row * N_DIM);
#pragma unroll
    for (int i = 0; i < 4; i++) {
        float4 f;
        f.x = e[i * 4 + 0] * inv; f.y = e[i * 4 + 1] * inv;
        f.z = e[i * 4 + 2] * inv; f.w = e[i * 4 + 3] * inv;
        o4[tid + 256 * i] = f;
    }
}

// ---------------------------------------------------------------------------
// Launch
// ---------------------------------------------------------------------------
extern "C" void kernel_launch(void* const* d_in, const int* in_sizes, int n_in,
                              void* d_out, int out_size) {
    const float* x = (const float*)d_in[0];   // [16384, 1024]
    const float* w = (const float*)d_in[1];   // [4096, 1024]
    float* out = (float*)d_out;               // [16384, 4096]

    const int smem_bytes = NSTAGES * STAGE_B;
    cudaFuncSetAttribute(gemm_f16_kernel,
                         cudaFuncAttributeMaxDynamicSharedMemorySize, smem_bytes);

    init_flags_kernel<<<1, 1>>>();
    scan_neg_kernel<<<256, 256>>>((const float4*)x, (M_DIM * K_DIM) / 4);
    rowsum_kernel<<<N_DIM, 128>>>(w);
    conv_x_kernel<<<2048, 256>>>((const float4*)x);
    conv_w_kernel<<<1024, 256>>>((const float4*)w);

    dim3 ggrid(N_DIM / 128, M_DIM / 128);
    gemm_f16_kernel<<<ggrid, 256, smem_bytes>>>(out);

    fixup_kernel<<<M_DIM, 256>>>(out, x, w, out);
}

// round 7
// speedup vs baseline: 4.3552x; 1.2871x over previous
#include <cuda_runtime.h>
#include <cuda_fp16.h>
#include <cstdint>

#define M_DIM 16384
#define N_DIM 4096
#define K_DIM 1024
#define TOPK  409

// ---------------------------------------------------------------------------
// Device scratch
// ---------------------------------------------------------------------------
__device__ int    g_has_neg;
__device__ float  g_S[N_DIM];                                // row sums of W
__device__ __half g_xh[(size_t)M_DIM * K_DIM];               // fp16 x
__device__ __half g_wh[(size_t)N_DIM * K_DIM];               // fp16 W

// ---------------------------------------------------------------------------
// K1: flag init
// ---------------------------------------------------------------------------
__global__ void init_flags_kernel() { g_has_neg = 0; }

// ---------------------------------------------------------------------------
// K2: fused fp32->fp16 conversion of x + negative scan
// ---------------------------------------------------------------------------
__global__ void __launch_bounds__(256)
conv_x_scan_kernel(const float4* __restrict__ src) {
    uint2* dst = (uint2*)g_xh;
    const int n4 = (M_DIM * K_DIM) / 4;
    bool neg = false;
    for (int i = blockIdx.x * blockDim.x + threadIdx.x; i < n4;
         i += gridDim.x * blockDim.x) {
        float4 v = src[i];
        neg |= (v.x < 0.f) | (v.y < 0.f) | (v.z < 0.f) | (v.w < 0.f);
        __half2 h01 = __floats2half2_rn(v.x, v.y);
        __half2 h23 = __floats2half2_rn(v.z, v.w);
        uint2 u;
        u.x = *(uint32_t*)&h01;
        u.y = *(uint32_t*)&h23;
        dst[i] = u;
    }
    if (__any_sync(0xFFFFFFFFu, neg) && (threadIdx.x & 31) == 0)
        g_has_neg = 1;
}

// ---------------------------------------------------------------------------
// K3: fused fp32->fp16 conversion of W + per-row sums. One block per W row.
// ---------------------------------------------------------------------------
__global__ void __launch_bounds__(256)
conv_w_rowsum_kernel(const float4* __restrict__ src) {
    __shared__ float ws[8];
    const int row = blockIdx.x;
    const int tid = threadIdx.x;
    const float4* s = src + (size_t)row * (K_DIM / 4);
    uint2* d = (uint2*)(g_wh + (size_t)row * K_DIM);

    float4 v = s[tid];
    float sum = v.x + v.y + v.z + v.w;
    __half2 h01 = __floats2half2_rn(v.x, v.y);
    __half2 h23 = __floats2half2_rn(v.z, v.w);
    uint2 u;
    u.x = *(uint32_t*)&h01;
    u.y = *(uint32_t*)&h23;
    d[tid] = u;

#pragma unroll
    for (int off = 16; off >= 1; off >>= 1)
        sum += __shfl_xor_sync(0xFFFFFFFFu, sum, off);
    if ((tid & 31) == 0) ws[tid >> 5] = sum;
    __syncthreads();
    if (tid == 0) {
        float t = 0.f;
#pragma unroll
        for (int w = 0; w < 8; w++) t += ws[w];
        g_S[row] = t;
    }
}

// ---------------------------------------------------------------------------
// K4: fp16 mma.sync GEMM  P[M,N] = xh[M,K] * wh[N,K]^T   (fp32 accumulate)
// ---------------------------------------------------------------------------
#define BKH 32
#define ROWB 80
#define NSTAGES 3
#define GCHUNKS (K_DIM / BKH)
#define ATILE_B (128 * ROWB)
#define STAGE_B (2 * ATILE_B)

#define CPA16(dst, src) \
    asm volatile("cp.async.cg.shared.global [%0], [%1], 16;" :: "r"(dst), "l"(src) : "memory")
#define CPA_COMMIT() asm volatile("cp.async.commit_group;" ::: "memory")
#define CPA_WAIT1()  asm volatile("cp.async.wait_group 1;" ::: "memory")

__device__ __forceinline__ uint32_t smem_u32(const void* p) {
    uint32_t a;
    asm("{ .reg .u64 t; cvta.to.shared.u64 t, %1; cvt.u32.u64 %0, t; }"
        : "=r"(a) : "l"(p));
    return a;
}

__device__ __forceinline__ void ldmx4(uint32_t r[4], uint32_t addr) {
    asm volatile("ldmatrix.sync.aligned.m8n8.x4.shared.b16 {%0,%1,%2,%3}, [%4];"
                 : "=r"(r[0]), "=r"(r[1]), "=r"(r[2]), "=r"(r[3]) : "r"(addr));
}

__device__ __forceinline__ void mma_f16(float c[4], const uint32_t a[4],
                                        const uint32_t b0, const uint32_t b1) {
    asm volatile(
        "mma.sync.aligned.m16n8k16.row.col.f32.f16.f16.f32 "
        "{%0,%1,%2,%3}, {%4,%5,%6,%7}, {%8,%9}, {%0,%1,%2,%3};"
        : "+f"(c[0]), "+f"(c[1]), "+f"(c[2]), "+f"(c[3])
        : "r"(a[0]), "r"(a[1]), "r"(a[2]), "r"(a[3]), "r"(b0), "r"(b1));
}

__global__ void __launch_bounds__(256, 2)
gemm_f16_kernel(float* __restrict__ C) {
    extern __shared__ char smem[];
    const uint32_t sbase = smem_u32(smem);

    const int tid  = threadIdx.x;
    const int wid  = tid >> 5;
    const int lane = tid & 31;
    const int g = lane >> 2;
    const int t = lane & 3;
    const int bm = blockIdx.y * 128;
    const int bn = blockIdx.x * 128;

    const int warp_m = (wid & 1) * 64;
    const int warp_n = (wid >> 1) * 32;

    const __half* Agbase = g_xh + (size_t)bm * K_DIM;
    const __half* Bgbase = g_wh + (size_t)bn * K_DIM;

    const int j8   = lane & 7;
    const int quad = lane >> 3;
    const int arow  = warp_m + ((quad & 1) << 3) + j8;
    const int akoff = (quad & 2) ? 16 : 0;
    const int brow  = warp_n + ((quad & 2) << 2) + j8;
    const int bkoff = (quad & 1) ? 16 : 0;

    uint32_t aoff[4], boff[2];
#pragma unroll
    for (int i = 0; i < 4; i++) aoff[i] = (uint32_t)((arow + i * 16) * ROWB + akoff);
#pragma unroll
    for (int jt = 0; jt < 2; jt++) boff[jt] = (uint32_t)((brow + jt * 16) * ROWB + bkoff);

    float acc[4][4][4];
#pragma unroll
    for (int i = 0; i < 4; i++)
#pragma unroll
        for (int j = 0; j < 4; j++)
#pragma unroll
            for (int q = 0; q < 4; q++) acc[i][j][q] = 0.f;

    auto issue = [&](int c, int s) {
        const uint32_t stA = sbase + s * STAGE_B;
        const uint32_t stB = stA + ATILE_B;
#pragma unroll
        for (int q = 0; q < 2; q++) {
            const int seg = tid + 256 * q;
            const int row = seg >> 2;
            const int c16 = seg & 3;
            const uint32_t doff = (uint32_t)(row * ROWB + c16 * 16);
            CPA16(stA + doff, Agbase + (size_t)row * K_DIM + c * BKH + c16 * 8);
            CPA16(stB + doff, Bgbase + (size_t)row * K_DIM + c * BKH + c16 * 8);
        }
    };

    issue(0, 0); CPA_COMMIT();
    issue(1, 1); CPA_COMMIT();

    for (int c = 0; c < GCHUNKS; ++c) {
        CPA_WAIT1();
        __syncthreads();

        const int cn = c + 2;
        if (cn < GCHUNKS) issue(cn, cn % NSTAGES);
        CPA_COMMIT();

        const uint32_t stA = sbase + (c % NSTAGES) * STAGE_B;
        const uint32_t stB = stA + ATILE_B;

#pragma unroll
        for (int ks = 0; ks < 2; ++ks) {
            uint32_t a[4][4], b[2][4];
#pragma unroll
            for (int i = 0; i < 4; i++)
                ldmx4(a[i], stA + aoff[i] + ks * 32);
#pragma unroll
            for (int jt = 0; jt < 2; jt++)
                ldmx4(b[jt], stB + boff[jt] + ks * 32);
#pragma unroll
            for (int i = 0; i < 4; i++) {
                mma_f16(acc[i][0], a[i], b[0][0], b[0][1]);
                mma_f16(acc[i][1], a[i], b[0][2], b[0][3]);
                mma_f16(acc[i][2], a[i], b[1][0], b[1][1]);
                mma_f16(acc[i][3], a[i], b[1][2], b[1][3]);
            }
        }
        __syncthreads();
    }

#pragma unroll
    for (int i = 0; i < 4; i++) {
#pragma unroll
        for (int j = 0; j < 4; j++) {
            const int r0 = bm + warp_m + i * 16 + g;
            const int cc = bn + warp_n + j * 8 + 2 * t;
            float2 v0 = {acc[i][j][0], acc[i][j][1]};
            float2 v1 = {acc[i][j][2], acc[i][j][3]};
            *(float2*)(C + (size_t)r0 * N_DIM + cc) = v0;
            *(float2*)(C + (size_t)(r0 + 8) * N_DIM + cc) = v1;
        }
    }
}

// ---------------------------------------------------------------------------
// K5: per-row exact top-K with approximate-GEMM fixup, then normalize.
// 2-pass radix (16-bit bucket) + parallel suffix-scan selection.
// ---------------------------------------------------------------------------
__device__ __forceinline__ unsigned float_to_key(float f) {
    unsigned u = __float_as_uint(f);
    return (u & 0x80000000u) ? ~u : (u | 0x80000000u);
}
__device__ __forceinline__ float key_to_float(unsigned k) {
    unsigned u = (k & 0x80000000u) ? (k ^ 0x80000000u) : ~k;
    return __uint_as_float(u);
}

#define CAND_CAP 192
#define MARGIN 0.0075f

__global__ void __launch_bounds__(256)
fixup_kernel(float* __restrict__ P, const float* __restrict__ X,
             const float* __restrict__ Wm, float* __restrict__ out) {
    __shared__ float    s_row[N_DIM];
    __shared__ float    s_xs[K_DIM];
    __shared__ unsigned char s_mask[N_DIM];
    __shared__ unsigned hist[256];
    __shared__ unsigned s_wtot[8];
    __shared__ unsigned s_woff[8];
    __shared__ unsigned s_prefix, s_rem;
    __shared__ int      s_cnt, s_nc;
    __shared__ int      s_cidx[CAND_CAP];
    __shared__ float    s_cval[CAND_CAP];
    __shared__ float    s_wsum[8];
    __shared__ float    s_inv;

    const int row = blockIdx.x;
    const int tid = threadIdx.x;
    const int wid = tid >> 5, lane = tid & 31;
    const bool bip = (g_has_neg == 0);

    const float4* p4 = (const float4*)(P + (size_t)row * N_DIM);

    float v[16];
#pragma unroll
    for (int i = 0; i < 4; i++) {
        float4 f = p4[tid + 256 * i];
        const int cb = (tid + 256 * i) * 4;
        if (bip) {
            f.x = 2.f * f.x - g_S[cb + 0];
            f.y = 2.f * f.y - g_S[cb + 1];
            f.z = 2.f * f.z - g_S[cb + 2];
            f.w = 2.f * f.w - g_S[cb + 3];
        }
        v[i * 4 + 0] = f.x; v[i * 4 + 1] = f.y;
        v[i * 4 + 2] = f.z; v[i * 4 + 3] = f.w;
        s_row[cb + 0] = f.x; s_row[cb + 1] = f.y;
        s_row[cb + 2] = f.z; s_row[cb + 3] = f.w;
    }

    unsigned key[16];
#pragma unroll
    for (int i = 0; i < 16; i++) key[i] = float_to_key(v[i]);

    // load x row concurrently (independent of select)
    for (int k = tid; k < K_DIM; k += 256) {
        float xv = X[(size_t)row * K_DIM + k];
        s_xs[k] = bip ? (xv - 0.5f) * 2.0f : xv;
    }
    if (tid == 0) { s_cnt = 0; s_nc = 0; s_prefix = 0; s_rem = TOPK; }

    // ---- 2-pass MSD radix select (top 16 key bits) ----
    unsigned prefix = 0;
    unsigned remaining = TOPK;
#pragma unroll
    for (int pass = 0; pass < 2; pass++) {
        const int shift = pass ? 16 : 24;
        hist[tid] = 0;
        __syncthreads();
#pragma unroll
        for (int i = 0; i < 16; i++) {
            bool part = pass ? ((key[i] & 0xFF000000u) == prefix) : true;
            if (part) atomicAdd(&hist[(key[i] >> shift) & 255u], 1u);
        }
        __syncthreads();

        // parallel inclusive suffix-sum over 256 bins
        unsigned sfx = hist[tid];
#pragma unroll
        for (int off = 1; off < 32; off <<= 1) {
            unsigned u = __shfl_down_sync(0xFFFFFFFFu, sfx, off);
            if (lane + off < 32) sfx += u;
        }
        if (lane == 0) s_wtot[wid] = sfx;
        __syncthreads();
        if (tid < 8) {
            unsigned t = s_wtot[tid];
#pragma unroll
            for (int off = 1; off < 8; off <<= 1) {
                unsigned u = __shfl_down_sync(0xFFu, t, off);
                if (tid + off < 8) t += u;
            }
            s_woff[tid] = t - s_wtot[tid];   // sum of warps strictly above
        }
        __syncthreads();
        const unsigned suffix = sfx + s_woff[wid];         // count(bins >= tid)
        unsigned nxt = __shfl_down_sync(0xFFFFFFFFu, suffix, 1);
        if (lane == 31) nxt = s_woff[wid];                 // suffix of tid+1
        if (suffix >= remaining && nxt < remaining) {
            s_prefix = prefix | ((unsigned)tid << shift);
            s_rem = remaining - nxt;                       // rank within this bucket
        }
        __syncthreads();
        prefix = s_prefix;
        remaining = s_rem;
        __syncthreads();
    }

    const float t_lo = key_to_float(prefix);
    const float t_hi = key_to_float(prefix | 0xFFFFu);
    const float hi = t_hi + MARGIN;
    const float lo = t_lo - MARGIN;

    // ---- candidates + sure count ----
    int myin = 0;
#pragma unroll
    for (int i = 0; i < 16; i++) {
        const int col = (tid + 256 * (i >> 2)) * 4 + (i & 3);
        const float val = v[i];
        const bool sure = (val > hi);
        s_mask[col] = sure ? 1 : 0;
        myin += sure ? 1 : 0;
        if (val <= hi && val >= lo) {
            int slot = atomicAdd(&s_nc, 1);
            if (slot < CAND_CAP) s_cidx[slot] = col;
        }
    }
#pragma unroll
    for (int off = 16; off >= 1; off >>= 1)
        myin += __shfl_xor_sync(0xFFFFFFFFu, myin, off);
    if (lane == 0) atomicAdd(&s_cnt, myin);
    __syncthreads();

    const int n_sure = s_cnt;
    const int n_c = min(s_nc, CAND_CAP);
    int need = TOPK - n_sure;
    if (need < 0) need = 0;
    if (need > n_c) need = n_c;

    // ---- exact fp32 dots for candidates (one warp per candidate) ----
    for (int j = wid; j < n_c; j += 8) {
        const int col = s_cidx[j];
        const float* wr = Wm + (size_t)col * K_DIM;
        float accv = 0.f;
#pragma unroll
        for (int i = 0; i < 32; i++) {
            const int k = lane + i * 32;
            accv = fmaf(s_xs[k], wr[k], accv);
        }
#pragma unroll
        for (int off = 16; off >= 1; off >>= 1)
            accv += __shfl_xor_sync(0xFFFFFFFFu, accv, off);
        if (lane == 0) {
            s_cval[j] = accv;
            s_row[col] = accv;
        }
    }
    __syncthreads();

    // ---- exact top-`need` among candidates ----
    if (tid < n_c) {
        const float vt = s_cval[tid];
        int rank = 0;
        for (int k = 0; k < n_c; k++) {
            const float vk = s_cval[k];
            rank += (vk > vt || (vk == vt && k < tid)) ? 1 : 0;
        }
        s_mask[s_cidx[tid]] = (rank < need) ? 1 : 0;
    }
    __syncthreads();

    // ---- encode + L2 normalize ----
    float e[16];
    float ss = 0.f;
#pragma unroll
    for (int i = 0; i < 16; i++) {
        const int col = (tid + 256 * (i >> 2)) * 4 + (i & 3);
        const float val = s_row[col];
        const float ev = s_mask[col] ? fmaxf(val, 0.f) : 0.f;
        e[i] = ev;
        ss = fmaf(ev, ev, ss);
    }
#pragma unroll
    for (int off = 16; off >= 1; off >>= 1)
        ss += __shfl_xor_sync(0xFFFFFFFFu, ss, off);
    if (lane == 0) s_wsum[wid] = ss;
    __syncthreads();
    if (tid == 0) {
        float tt = 0.f;
#pragma unroll
        for (int w = 0; w < 8; w++) tt += s_wsum[w];
        s_inv = 1.0f / fmaxf(sqrtf(tt), 1e-12f);
    }
    __syncthreads();
    const float inv = s_inv;

    float4* o4 = (float4*)(out + (size_t)row * N_DIM);
#pragma unroll
    for (int i = 0; i < 4; i++) {
        float4 f;
        f.x = e[i * 4 + 0] * inv; f.y = e[i * 4 + 1] * inv;
        f.z = e[i * 4 + 2] * inv; f.w = e[i * 4 + 3] * inv;
        o4[tid + 256 * i] = f;
    }
}

// ---------------------------------------------------------------------------
// Launch
// ---------------------------------------------------------------------------
extern "C" void kernel_launch(void* const* d_in, const int* in_sizes, int n_in,
                              void* d_out, int out_size) {
    const float* x = (const float*)d_in[0];   // [16384, 1024]
    const float* w = (const float*)d_in[1];   // [4096, 1024]
    float* out = (float*)d_out;               // [16384, 4096]

    const int smem_bytes = NSTAGES * STAGE_B;
    cudaFuncSetAttribute(gemm_f16_kernel,
                         cudaFuncAttributeMaxDynamicSharedMemorySize, smem_bytes);

    init_flags_kernel<<<1, 1>>>();
    conv_x_scan_kernel<<<2048, 256>>>((const float4*)x);
    conv_w_rowsum_kernel<<<N_DIM, 256>>>((const float4*)w);

    dim3 ggrid(N_DIM / 128, M_DIM / 128);
    gemm_f16_kernel<<<ggrid, 256, smem_bytes>>>(out);

    fixup_kernel<<<M_DIM, 256>>>(out, x, w, out);
}